// round 10
// baseline (speedup 1.0000x reference)
#include <cuda_runtime.h>
#include <cuda_bf16.h>

// Balloon-Windkessel BOLD, 1000 Euler steps — parallel-in-time, v4.
// THREE scan passes:
//   Pass 1: Newton sweep for v from lag-corrected warm start (err 1e-2 -> ~1e-4)
//   Pass 2: Newton sweep (err ~1e-4 -> ~1e-8)
//   Pass 3: FUSED dual scan: final Newton sweep for v (exact in fp32) + exact
//           q-scan whose coefficients use the pass-2 v (err 1e-8 -> negligible).
// 6 __syncthreads total. Thread t owns step t; block = 1024 threads.

#define N_STEPS 1000
#define NT      1024
#define DT      0.01f
#define RHO     0.34f
#define ALPHA   0.32f

#define LOG2R   (-0.0071769220f)   // log2(sqrt(1 - h + h^2)), h = 0.01
#define THETA   (0.0087035531f)    // atan2(sqrt(3)/2*h, 1 - h/2)
#define INVSQ3  (0.57735026919f)
#define TWOSQ3  (1.15470053838f)   // 2/sqrt(3)
#define L66     (-0.5994621118f)   // log2(0.66)
#define A2      (ALPHA*ALPHA)      // 0.1024
#define PEXP    (2.0f*ALPHA-2.0f)  // -1.36

#define YC   0.0972f
#define YK1  0.0476f
#define YK2  0.04f
#define YK3  0.0096f

__device__ __forceinline__ float ex2a(float x){ float r; asm("ex2.approx.f32 %0,%1;":"=f"(r):"f"(x)); return r; }
__device__ __forceinline__ float lg2a(float x){ float r; asm("lg2.approx.f32 %0,%1;":"=f"(r):"f"(x)); return r; }
__device__ __forceinline__ float sina(float x){ float r; asm("sin.approx.f32 %0,%1;":"=f"(r):"f"(x)); return r; }
__device__ __forceinline__ float cosa(float x){ float r; asm("cos.approx.f32 %0,%1;":"=f"(r):"f"(x)); return r; }
__device__ __forceinline__ float rcpa(float x){ float r; asm("rcp.approx.f32 %0,%1;":"=f"(r):"f"(x)); return r; }

// Affine block scan; returns inclusive (A,B) and exclusive (exA,exB).
// Exactly 2 __syncthreads; sA/sB must alternate between calls.
__device__ __forceinline__ void scan1(float& A, float& B, float& exA, float& exB,
                                      int lane, int warp, float* sA, float* sB) {
    #pragma unroll
    for (int d = 1; d < 32; d <<= 1) {
        float pA = __shfl_up_sync(0xffffffffu, A, d);
        float pB = __shfl_up_sync(0xffffffffu, B, d);
        if (lane >= d) { B = fmaf(A, pB, B); A = A * pA; }
    }
    if (lane == 31) { sA[warp] = A; sB[warp] = B; }
    __syncthreads();
    if (warp == 0) {
        float wA = sA[lane], wB = sB[lane];
        #pragma unroll
        for (int d = 1; d < 32; d <<= 1) {
            float pA = __shfl_up_sync(0xffffffffu, wA, d);
            float pB = __shfl_up_sync(0xffffffffu, wB, d);
            if (lane >= d) { wB = fmaf(wA, pB, wB); wA = wA * pA; }
        }
        sA[lane] = wA; sB[lane] = wB;
    }
    __syncthreads();
    float pA = 1.0f, pB = 0.0f;
    if (warp > 0) { pA = sA[warp - 1]; pB = sB[warp - 1]; }
    B = fmaf(A, pB, B);
    A = A * pA;
    exA = __shfl_up_sync(0xffffffffu, A, 1);
    exB = __shfl_up_sync(0xffffffffu, B, 1);
    if (lane == 0) { exA = pA; exB = pB; }
}

// Dual affine scan (two independent maps), inclusive only.
__device__ __forceinline__ void scan2(float& A, float& B, float& C, float& D,
                                      int lane, int warp,
                                      float* sA, float* sB, float* sC, float* sD) {
    #pragma unroll
    for (int d = 1; d < 32; d <<= 1) {
        float pA = __shfl_up_sync(0xffffffffu, A, d);
        float pB = __shfl_up_sync(0xffffffffu, B, d);
        float pC = __shfl_up_sync(0xffffffffu, C, d);
        float pD = __shfl_up_sync(0xffffffffu, D, d);
        if (lane >= d) {
            B = fmaf(A, pB, B); A = A * pA;
            D = fmaf(C, pD, D); C = C * pC;
        }
    }
    if (lane == 31) { sA[warp] = A; sB[warp] = B; sC[warp] = C; sD[warp] = D; }
    __syncthreads();
    if (warp == 0) {
        float wA = sA[lane], wB = sB[lane], wC = sC[lane], wD = sD[lane];
        #pragma unroll
        for (int d = 1; d < 32; d <<= 1) {
            float pA = __shfl_up_sync(0xffffffffu, wA, d);
            float pB = __shfl_up_sync(0xffffffffu, wB, d);
            float pC = __shfl_up_sync(0xffffffffu, wC, d);
            float pD = __shfl_up_sync(0xffffffffu, wD, d);
            if (lane >= d) {
                wB = fmaf(wA, pB, wB); wA = wA * pA;
                wD = fmaf(wC, pD, wD); wC = wC * pC;
            }
        }
        sA[lane] = wA; sB[lane] = wB; sC[lane] = wC; sD[lane] = wD;
    }
    __syncthreads();
    if (warp > 0) {
        float pA = sA[warp - 1], pB = sB[warp - 1];
        float pC = sC[warp - 1], pD = sD[warp - 1];
        B = fmaf(A, pB, B); A = A * pA;
        D = fmaf(C, pD, D); C = C * pC;
    }
}

__global__ void __launch_bounds__(NT, 1)
bold_pits_kernel(const float* __restrict__ mtt_ptr, float* __restrict__ y_out) {
    __shared__ float s0[32], s1[32], s2[32], s3[32], s4[32], s5[32];

    const int t    = threadIdx.x;
    const int lane = t & 31;
    const int warp = t >> 5;
    const bool active = (t < N_STEPS);

    const float mtt = mtt_ptr[0];
    const float dtm = DT / mtt;

    // ---- elementwise: f, s, E, coefficients, lag-corrected warm start -----
    float a_t = 0.0f, g_t = 0.0f, vk = 1.0f;
    if (active) {
        float tf  = (float)t;
        float rp  = ex2a(LOG2R * tf);                  // r^t
        float ang = THETA * tf;
        float sn  = sina(ang);
        float f   = 2.0f - rp * fmaf(sn, INVSQ3, cosa(ang));
        float s_t = TWOSQ3 * rp * sn;                  // closed-form s_t
        float E   = 1.0f - ex2a(L66 * rcpa(f));
        a_t = dtm * f;
        g_t = (dtm / RHO) * f * E;
        float lgf = lg2a(f);
        float fa  = ex2a(ALPHA * lgf);                 // f^alpha
        float fp  = ex2a(PEXP * lgf);                  // f^(2a-2)
        vk = fmaf(-mtt * A2 * s_t, fp, fa);            // warm start, err ~1e-2
    }

    // ---- Pass 1: Newton sweep for v (err -> ~1e-4) ------------------------
    {
        float A = 1.0f, B = 0.0f, exA, exB;
        if (active) {
            float u  = ex2a(2.125f * lg2a(vk));        // vk^2.125
            float du = dtm * u;
            A = fmaf(-3.125f, du, 1.0f);
            B = fmaf(2.125f * vk, du, a_t);
        }
        scan1(A, B, exA, exB, lane, warp, s0, s1);
        vk = exA + exB;
    }

    // ---- Pass 2: Newton sweep for v (err -> ~1e-8) ------------------------
    {
        float A = 1.0f, B = 0.0f, exA, exB;
        if (active) {
            float u  = ex2a(2.125f * lg2a(vk));
            float du = dtm * u;
            A = fmaf(-3.125f, du, 1.0f);
            B = fmaf(2.125f * vk, du, a_t);
        }
        scan1(A, B, exA, exB, lane, warp, s2, s3);
        vk = exA + exB;
    }

    // ---- Pass 3: fused final Newton sweep (v) + exact q-scan --------------
    float Av = 1.0f, Bv = 0.0f, Aq = 1.0f, Bq = 0.0f;
    if (active) {
        float u  = ex2a(2.125f * lg2a(vk));            // v_t^2.125 (shared)
        float du = dtm * u;
        Av = fmaf(-3.125f, du, 1.0f);
        Bv = fmaf(2.125f * vk, du, a_t);
        Aq = 1.0f - du;
        Bq = g_t;
    }
    scan2(Av, Bv, Aq, Bq, lane, warp, s4, s5, s0, s1);
    float v_next = Av + Bv;                            // v_{t+1} (v_0 = 1)
    float q_next = Aq + Bq;                            // q_{t+1} (q_0 = 1)

    // ---- BOLD readout ------------------------------------------------------
    if (active) {
        float yt = fmaf(-YK1, q_next, YC);
        yt = fmaf(-YK3, v_next, yt);
        yt = fmaf(-YK2, q_next * rcpa(v_next), yt);
        y_out[t] = yt;
    }
}

extern "C" void kernel_launch(void* const* d_in, const int* in_sizes, int n_in,
                              void* d_out, int out_size) {
    const float* mtt = (const float*)d_in[0];
    float* y = (float*)d_out;
    bold_pits_kernel<<<1, NT>>>(mtt, y);
}

// round 15
// speedup vs baseline: 1.1635x; 1.1635x over previous
#include <cuda_runtime.h>
#include <cuda_bf16.h>

// Balloon-Windkessel BOLD, 1000 Euler steps — parallel-in-time, v5 (chunked).
// 256 threads (8 warps), thread t owns steps 4t..4t+3.
// Same math as v4: warm start -> 2 Newton affine-scan sweeps for v -> fused
// dual scan (final Newton v + exact q). Chunking shrinks every block scan:
// 8-warp barriers, 3-level cross-warp scan, 4-step local compose/replay.

#define N_STEPS 1000
#define NT      256
#define CHUNK   4
#define NW      (NT/32)
#define DT      0.01f
#define RHO     0.34f
#define ALPHA   0.32f

#define LOG2R   (-0.0071769220f)   // log2(sqrt(1 - h + h^2)), h = 0.01
#define THETA   (0.0087035531f)    // atan2(sqrt(3)/2*h, 1 - h/2)
#define INVSQ3  (0.57735026919f)
#define TWOSQ3  (1.15470053838f)   // 2/sqrt(3)
#define L66     (-0.5994621118f)   // log2(0.66)
#define A2      (ALPHA*ALPHA)      // 0.1024
#define PEXP    (2.0f*ALPHA-2.0f)  // -1.36

#define YC   0.0972f
#define YK1  0.0476f
#define YK2  0.04f
#define YK3  0.0096f

__device__ __forceinline__ float ex2a(float x){ float r; asm("ex2.approx.f32 %0,%1;":"=f"(r):"f"(x)); return r; }
__device__ __forceinline__ float lg2a(float x){ float r; asm("lg2.approx.f32 %0,%1;":"=f"(r):"f"(x)); return r; }
__device__ __forceinline__ float sina(float x){ float r; asm("sin.approx.f32 %0,%1;":"=f"(r):"f"(x)); return r; }
__device__ __forceinline__ float cosa(float x){ float r; asm("cos.approx.f32 %0,%1;":"=f"(r):"f"(x)); return r; }
__device__ __forceinline__ float rcpa(float x){ float r; asm("rcp.approx.f32 %0,%1;":"=f"(r):"f"(x)); return r; }

// Block scan of affine maps over 8 warps; returns inclusive and exclusive.
// 2 __syncthreads; sA/sB must alternate between calls.
__device__ __forceinline__ void scan1(float& A, float& B, float& exA, float& exB,
                                      int lane, int warp, float* sA, float* sB) {
    #pragma unroll
    for (int d = 1; d < 32; d <<= 1) {
        float pA = __shfl_up_sync(0xffffffffu, A, d);
        float pB = __shfl_up_sync(0xffffffffu, B, d);
        if (lane >= d) { B = fmaf(A, pB, B); A = A * pA; }
    }
    if (lane == 31) { sA[warp] = A; sB[warp] = B; }
    __syncthreads();
    if (warp == 0) {
        float wA = (lane < NW) ? sA[lane] : 1.0f;
        float wB = (lane < NW) ? sB[lane] : 0.0f;
        #pragma unroll
        for (int d = 1; d < NW; d <<= 1) {
            float pA = __shfl_up_sync(0xffffffffu, wA, d);
            float pB = __shfl_up_sync(0xffffffffu, wB, d);
            if (lane >= d) { wB = fmaf(wA, pB, wB); wA = wA * pA; }
        }
        if (lane < NW) { sA[lane] = wA; sB[lane] = wB; }
    }
    __syncthreads();
    float pA = 1.0f, pB = 0.0f;
    if (warp > 0) { pA = sA[warp - 1]; pB = sB[warp - 1]; }
    B = fmaf(A, pB, B);
    A = A * pA;
    exA = __shfl_up_sync(0xffffffffu, A, 1);
    exB = __shfl_up_sync(0xffffffffu, B, 1);
    if (lane == 0) { exA = pA; exB = pB; }
}

// Dual affine block scan; returns exclusive prefixes for both maps.
__device__ __forceinline__ void scan2(float& A, float& B, float& C, float& D,
                                      float& exA, float& exB, float& exC, float& exD,
                                      int lane, int warp,
                                      float* sA, float* sB, float* sC, float* sD) {
    #pragma unroll
    for (int d = 1; d < 32; d <<= 1) {
        float pA = __shfl_up_sync(0xffffffffu, A, d);
        float pB = __shfl_up_sync(0xffffffffu, B, d);
        float pC = __shfl_up_sync(0xffffffffu, C, d);
        float pD = __shfl_up_sync(0xffffffffu, D, d);
        if (lane >= d) {
            B = fmaf(A, pB, B); A = A * pA;
            D = fmaf(C, pD, D); C = C * pC;
        }
    }
    if (lane == 31) { sA[warp] = A; sB[warp] = B; sC[warp] = C; sD[warp] = D; }
    __syncthreads();
    if (warp == 0) {
        float wA = (lane < NW) ? sA[lane] : 1.0f;
        float wB = (lane < NW) ? sB[lane] : 0.0f;
        float wC = (lane < NW) ? sC[lane] : 1.0f;
        float wD = (lane < NW) ? sD[lane] : 0.0f;
        #pragma unroll
        for (int d = 1; d < NW; d <<= 1) {
            float pA = __shfl_up_sync(0xffffffffu, wA, d);
            float pB = __shfl_up_sync(0xffffffffu, wB, d);
            float pC = __shfl_up_sync(0xffffffffu, wC, d);
            float pD = __shfl_up_sync(0xffffffffu, wD, d);
            if (lane >= d) {
                wB = fmaf(wA, pB, wB); wA = wA * pA;
                wD = fmaf(wC, pD, wD); wC = wC * pC;
            }
        }
        if (lane < NW) { sA[lane] = wA; sB[lane] = wB; sC[lane] = wC; sD[lane] = wD; }
    }
    __syncthreads();
    float pA = 1.0f, pB = 0.0f, pC = 1.0f, pD = 0.0f;
    if (warp > 0) { pA = sA[warp-1]; pB = sB[warp-1]; pC = sC[warp-1]; pD = sD[warp-1]; }
    B = fmaf(A, pB, B); A = A * pA;
    D = fmaf(C, pD, D); C = C * pC;
    exA = __shfl_up_sync(0xffffffffu, A, 1);
    exB = __shfl_up_sync(0xffffffffu, B, 1);
    exC = __shfl_up_sync(0xffffffffu, C, 1);
    exD = __shfl_up_sync(0xffffffffu, D, 1);
    if (lane == 0) { exA = pA; exB = pB; exC = pC; exD = pD; }
}

__global__ void __launch_bounds__(NT, 1)
bold_pits_kernel(const float* __restrict__ mtt_ptr, float* __restrict__ y_out) {
    __shared__ float s0[NW], s1[NW], s2[NW], s3[NW], s4[NW], s5[NW], s6[NW], s7[NW];

    const int tid  = threadIdx.x;
    const int lane = tid & 31;
    const int warp = tid >> 5;
    const int base = tid * CHUNK;
    const bool active = (base < N_STEPS);      // 250 threads fully active

    const float mtt = mtt_ptr[0];
    const float dtm = DT / mtt;

    // ---- elementwise per-step coefficients + warm start (4-way ILP) -------
    float a[CHUNK], g[CHUNK], vk[CHUNK];
    #pragma unroll
    for (int j = 0; j < CHUNK; ++j) { a[j] = 0.0f; g[j] = 0.0f; vk[j] = 1.0f; }
    if (active) {
        #pragma unroll
        for (int j = 0; j < CHUNK; ++j) {
            float tf  = (float)(base + j);
            float rp  = ex2a(LOG2R * tf);
            float ang = THETA * tf;
            float sn  = sina(ang);
            float f   = 2.0f - rp * fmaf(sn, INVSQ3, cosa(ang));
            float s_t = TWOSQ3 * rp * sn;
            float E   = 1.0f - ex2a(L66 * rcpa(f));
            a[j] = dtm * f;
            g[j] = (dtm / RHO) * f * E;
            float lgf = lg2a(f);
            float fa  = ex2a(ALPHA * lgf);
            float fp  = ex2a(PEXP * lgf);
            vk[j] = fmaf(-mtt * A2 * s_t, fp, fa);
        }
    }

    // ---- Passes 1 & 2: Newton sweeps for v --------------------------------
    #pragma unroll
    for (int pass = 0; pass < 2; ++pass) {
        float As[CHUNK], Bs[CHUNK];
        float A = 1.0f, B = 0.0f;
        if (active) {
            #pragma unroll
            for (int j = 0; j < CHUNK; ++j) {
                float u  = ex2a(2.125f * lg2a(vk[j]));
                float du = dtm * u;
                As[j] = fmaf(-3.125f, du, 1.0f);
                Bs[j] = fmaf(2.125f * vk[j], du, a[j]);
                B = fmaf(As[j], B, Bs[j]);     // compose chunk map
                A = A * As[j];
            }
        } else {
            #pragma unroll
            for (int j = 0; j < CHUNK; ++j) { As[j] = 1.0f; Bs[j] = 0.0f; }
        }
        float exA, exB;
        if (pass) scan1(A, B, exA, exB, lane, warp, s2, s3);
        else      scan1(A, B, exA, exB, lane, warp, s0, s1);
        float v = exA + exB;                   // v at chunk start (v_0 = 1)
        if (active) {
            #pragma unroll
            for (int j = 0; j < CHUNK; ++j) {  // replay: refined v per step
                vk[j] = v;
                v = fmaf(As[j], v, Bs[j]);
            }
        }
    }

    // ---- Pass 3: fused final Newton (v) + exact q-scan --------------------
    float Avs[CHUNK], Bvs[CHUNK], Aqs[CHUNK], Bqs[CHUNK];
    float Av = 1.0f, Bv = 0.0f, Aq = 1.0f, Bq = 0.0f;
    if (active) {
        #pragma unroll
        for (int j = 0; j < CHUNK; ++j) {
            float u  = ex2a(2.125f * lg2a(vk[j]));
            float du = dtm * u;
            Avs[j] = fmaf(-3.125f, du, 1.0f);
            Bvs[j] = fmaf(2.125f * vk[j], du, a[j]);
            Aqs[j] = 1.0f - du;
            Bqs[j] = g[j];
            Bv = fmaf(Avs[j], Bv, Bvs[j]); Av = Av * Avs[j];
            Bq = fmaf(Aqs[j], Bq, Bqs[j]); Aq = Aq * Aqs[j];
        }
    } else {
        #pragma unroll
        for (int j = 0; j < CHUNK; ++j) { Avs[j]=1.0f; Bvs[j]=0.0f; Aqs[j]=1.0f; Bqs[j]=0.0f; }
    }
    float exAv, exBv, exAq, exBq;
    scan2(Av, Bv, Aq, Bq, exAv, exBv, exAq, exBq, lane, warp, s4, s5, s6, s7);

    // ---- replay + BOLD readout, one float4 store per thread ---------------
    if (active) {
        float v = exAv + exBv;                 // v at chunk start
        float q = exAq + exBq;                 // q at chunk start
        float4 y4;
        float yv[CHUNK];
        #pragma unroll
        for (int j = 0; j < CHUNK; ++j) {
            v = fmaf(Avs[j], v, Bvs[j]);       // v_{t+1}
            q = fmaf(Aqs[j], q, Bqs[j]);       // q_{t+1}
            float yt = fmaf(-YK1, q, YC);
            yt = fmaf(-YK3, v, yt);
            yt = fmaf(-YK2, q * rcpa(v), yt);
            yv[j] = yt;
        }
        y4.x = yv[0]; y4.y = yv[1]; y4.z = yv[2]; y4.w = yv[3];
        reinterpret_cast<float4*>(y_out)[tid] = y4;
    }
}

extern "C" void kernel_launch(void* const* d_in, const int* in_sizes, int n_in,
                              void* d_out, int out_size) {
    const float* mtt = (const float*)d_in[0];
    float* y = (float*)d_out;
    bold_pits_kernel<<<1, NT>>>(mtt, y);
}